// round 11
// baseline (speedup 1.0000x reference)
#include <cuda_runtime.h>
#include <cuda_bf16.h>
#include <cstdint>

// ===========================================================================
// ChannelAttentionModule (DANet), B=32, C=512, N=H*W=1024, fp32.
//   S = feat @ feat^T ; W = softmax(rowmax(S)-S) = exp(rowmin-S)/sum ;
//   out = beta * (W @ feat) + x
// R11: av_mma upgraded to 128x256 CTA tile (BK=16, 2-stage, 48KB smem):
//   2x compute per barrier, half the syncs, half the A traffic.
// gram keeps R10's 3-stage 128x128 fused 3-term pipeline.
// ===========================================================================

#define BDIM 32
#define CDIM 512
#define NDIM 1024
#define TSZ  2048                  // shorts per 128x16 tile (no padding)
#define BTSZ 4096                  // shorts per 256x16 tile

// ---------------- scratch (static device globals: allowed) ----------------
__device__ float          g_scores[(size_t)BDIM * CDIM * CDIM];
__device__ __align__(16) unsigned short g_h [(size_t)BDIM * CDIM * NDIM]; // x hi  [b][c][n]
__device__ __align__(16) unsigned short g_l [(size_t)BDIM * CDIM * NDIM]; // x lo
__device__ __align__(16) unsigned short g_th[(size_t)BDIM * NDIM * CDIM]; // x^T hi [b][n][c]
__device__ __align__(16) unsigned short g_tl[(size_t)BDIM * NDIM * CDIM]; // x^T lo
__device__ __align__(16) unsigned short g_wh[(size_t)BDIM * CDIM * CDIM]; // W hi  [b][c][d]
__device__ __align__(16) unsigned short g_wl[(size_t)BDIM * CDIM * CDIM]; // W lo

// ---------------- helpers ---------------------------------------------------
__device__ __forceinline__ uint32_t smem_u32(const void* p) {
    uint32_t a;
    asm("{ .reg .u64 t; cvta.to.shared.u64 t, %1; cvt.u32.u64 %0, t; }"
        : "=r"(a) : "l"(p));
    return a;
}
__device__ __forceinline__ void ldsm4(uint32_t r[4], uint32_t addr) {
    asm volatile("ldmatrix.sync.aligned.m8n8.x4.shared.b16 {%0,%1,%2,%3}, [%4];"
                 : "=r"(r[0]), "=r"(r[1]), "=r"(r[2]), "=r"(r[3]) : "r"(addr));
}
__device__ __forceinline__ void mma16816(float d[4], const uint32_t a[4],
                                         const uint32_t b[2]) {
    asm volatile(
        "mma.sync.aligned.m16n8k16.row.col.f32.bf16.bf16.f32 "
        "{%0,%1,%2,%3}, {%4,%5,%6,%7}, {%8,%9}, {%0,%1,%2,%3};"
        : "+f"(d[0]), "+f"(d[1]), "+f"(d[2]), "+f"(d[3])
        : "r"(a[0]), "r"(a[1]), "r"(a[2]), "r"(a[3]), "r"(b[0]), "r"(b[1]));
}
__device__ __forceinline__ void cpa(uint32_t s, const void* g) {
    asm volatile("cp.async.cg.shared.global [%0], [%1], 16;" :: "r"(s), "l"(g));
}
#define CPC()  asm volatile("cp.async.commit_group;" ::: "memory")
#define CPW(n) asm volatile("cp.async.wait_group %0;" :: "n"(n) : "memory")

// Tile-local byte offset for (row, k-half): row stride 32B, halves swap
// every 4 rows -> conflict-free cp.async stores and ldmatrix reads.
__device__ __forceinline__ uint32_t tswz(int row, int kh) {
    return (uint32_t)(row * 32 + ((kh ^ ((row >> 2) & 1)) << 4));
}

__device__ __forceinline__ void bsplit(float v, unsigned short& h, unsigned short& l) {
    __nv_bfloat16 hh = __float2bfloat16_rn(v);
    float r = v - __bfloat162float(hh);
    __nv_bfloat16 ll = __float2bfloat16_rn(r);
    h = *reinterpret_cast<unsigned short*>(&hh);
    l = *reinterpret_cast<unsigned short*>(&ll);
}

// ===========================================================================
// Fused 3-term 128x128 GEMM mainloop, 3-stage pipeline (gram).
// ===========================================================================
template <int NC, int LD>
__device__ __forceinline__ void gemm3(
    const unsigned short* __restrict__ Ah, const unsigned short* __restrict__ Al,
    const unsigned short* __restrict__ Bh, const unsigned short* __restrict__ Bl,
    unsigned short (*S)[4][TSZ],            // [3][4][TSZ]
    float acc[4][4][4])
{
    const int t = threadIdx.x, lane = t & 31, wid = t >> 5;
    const int crow = t >> 1, ckh = t & 1;
    const size_t goff = (size_t)crow * LD + ckh * 8;
    const uint32_t soff = tswz(crow, ckh);

    const int wm = (wid & 1) * 64, wn = (wid >> 1) * 32;
    const int a_r = wm + (lane & 15), a_kh = lane >> 4;
    const int b_r = wn + (lane & 7) + ((lane >> 4) << 3), b_kh = (lane >> 3) & 1;

    const unsigned short* src[4] = { Ah, Al, Bh, Bl };

#pragma unroll
    for (int pc = 0; pc < 2; pc++) {
        if (pc < NC) {
#pragma unroll
            for (int tau = 0; tau < 4; tau++)
                cpa(smem_u32(&S[pc][tau][0]) + soff, src[tau] + goff + pc * 16);
            CPC();
        }
    }

    for (int c = 0; c < NC; c++) {
        if (c + 1 < NC) { CPW(1); } else { CPW(0); }
        __syncthreads();
        if (c + 2 < NC) {
            const int nb = (c + 2) % 3;
            const size_t go = goff + (size_t)(c + 2) * 16;
#pragma unroll
            for (int tau = 0; tau < 4; tau++)
                cpa(smem_u32(&S[nb][tau][0]) + soff, src[tau] + go);
            CPC();
        }

        const int cb = c % 3;
        const uint32_t bAh = smem_u32(&S[cb][0][0]);
        const uint32_t bAl = smem_u32(&S[cb][1][0]);
        const uint32_t bBh = smem_u32(&S[cb][2][0]);
        const uint32_t bBl = smem_u32(&S[cb][3][0]);

        uint32_t AhF[4][4], AlF[4][4], BhF[2][4], BlF[2][4];
#pragma unroll
        for (int mi = 0; mi < 4; mi++)
            ldsm4(AhF[mi], bAh + tswz(a_r + 16 * mi, a_kh));
#pragma unroll
        for (int nj = 0; nj < 2; nj++)
            ldsm4(BhF[nj], bBh + tswz(b_r + 16 * nj, b_kh));
#pragma unroll
        for (int mi = 0; mi < 4; mi++)
#pragma unroll
            for (int ni = 0; ni < 4; ni++)
                mma16816(acc[mi][ni], AhF[mi], &BhF[ni >> 1][(ni & 1) * 2]);
#pragma unroll
        for (int nj = 0; nj < 2; nj++)
            ldsm4(BlF[nj], bBl + tswz(b_r + 16 * nj, b_kh));
#pragma unroll
        for (int mi = 0; mi < 4; mi++)
#pragma unroll
            for (int ni = 0; ni < 4; ni++)
                mma16816(acc[mi][ni], AhF[mi], &BlF[ni >> 1][(ni & 1) * 2]);
#pragma unroll
        for (int mi = 0; mi < 4; mi++)
            ldsm4(AlF[mi], bAl + tswz(a_r + 16 * mi, a_kh));
#pragma unroll
        for (int mi = 0; mi < 4; mi++)
#pragma unroll
            for (int ni = 0; ni < 4; ni++)
                mma16816(acc[mi][ni], AlF[mi], &BhF[ni >> 1][(ni & 1) * 2]);
    }
}

// ===========================================================================
// Stage 0: split + transpose:  x -> g_h/g_l ([c][n])  and  g_th/g_tl ([n][c])
// ===========================================================================
__global__ void prep_kernel(const float* __restrict__ x) {
    const int b = blockIdx.z, c0 = blockIdx.y * 32, n0 = blockIdx.x * 32;
    __shared__ float tile[32][33];
    const int t = threadIdx.x;
    const int i = t >> 3, j0 = (t & 7) * 4;

    const size_t src = ((size_t)(b * CDIM + c0 + i) * NDIM) + n0 + j0;
    float4 v = *(const float4*)(x + src);
    tile[i][j0 + 0] = v.x; tile[i][j0 + 1] = v.y;
    tile[i][j0 + 2] = v.z; tile[i][j0 + 3] = v.w;

    unsigned short h[4], l[4];
    bsplit(v.x, h[0], l[0]); bsplit(v.y, h[1], l[1]);
    bsplit(v.z, h[2], l[2]); bsplit(v.w, h[3], l[3]);
    uint2 ph, pl;
    ph.x = h[0] | ((uint32_t)h[1] << 16); ph.y = h[2] | ((uint32_t)h[3] << 16);
    pl.x = l[0] | ((uint32_t)l[1] << 16); pl.y = l[2] | ((uint32_t)l[3] << 16);
    *(uint2*)(g_h + src) = ph;
    *(uint2*)(g_l + src) = pl;

    __syncthreads();

    float f0 = tile[j0 + 0][i], f1 = tile[j0 + 1][i];
    float f2 = tile[j0 + 2][i], f3 = tile[j0 + 3][i];
    bsplit(f0, h[0], l[0]); bsplit(f1, h[1], l[1]);
    bsplit(f2, h[2], l[2]); bsplit(f3, h[3], l[3]);
    ph.x = h[0] | ((uint32_t)h[1] << 16); ph.y = h[2] | ((uint32_t)h[3] << 16);
    pl.x = l[0] | ((uint32_t)l[1] << 16); pl.y = l[2] | ((uint32_t)l[3] << 16);
    const size_t dst = ((size_t)(b * NDIM + n0 + i) * CDIM) + c0 + j0;
    *(uint2*)(g_th + dst) = ph;
    *(uint2*)(g_tl + dst) = pl;
}

// ===========================================================================
// Stage 1: Gram S = F F^T. 10 upper-tri 128x128 tile pairs, mirrored.
// ===========================================================================
__global__ __launch_bounds__(256, 2)
void gram_mma() {
    __shared__ unsigned short S[3][4][TSZ];      // exactly 48 KB

    const int b = blockIdx.y;
    int p = blockIdx.x;
    int ti = 0;
    while (p >= 4 - ti) { p -= 4 - ti; ti++; }
    const int tj = ti + p;

    const unsigned short* Ah = g_h + (size_t)(b * CDIM + ti * 128) * NDIM;
    const unsigned short* Al = g_l + (size_t)(b * CDIM + ti * 128) * NDIM;
    const unsigned short* Bh = g_h + (size_t)(b * CDIM + tj * 128) * NDIM;
    const unsigned short* Bl = g_l + (size_t)(b * CDIM + tj * 128) * NDIM;

    float acc[4][4][4];
#pragma unroll
    for (int i = 0; i < 4; i++)
#pragma unroll
        for (int j = 0; j < 4; j++)
#pragma unroll
            for (int k = 0; k < 4; k++) acc[i][j][k] = 0.f;

    gemm3<64, NDIM>(Ah, Al, Bh, Bl, S, acc);

    const int lane = threadIdx.x & 31, wid = threadIdx.x >> 5;
    const int wm = (wid & 1) * 64, wn = (wid >> 1) * 32;
    float* Cb = g_scores + (size_t)b * CDIM * CDIM;
    const int r0 = ti * 128 + wm + (lane >> 2);
    const int c0 = tj * 128 + wn + 2 * (lane & 3);
#pragma unroll
    for (int mi = 0; mi < 4; mi++)
#pragma unroll
        for (int ni = 0; ni < 4; ni++) {
            const float* d = acc[mi][ni];
            const int gr = r0 + 16 * mi, gc = c0 + 8 * ni;
            *(float2*)&Cb[(size_t)gr * CDIM + gc]       = make_float2(d[0], d[1]);
            *(float2*)&Cb[(size_t)(gr + 8) * CDIM + gc] = make_float2(d[2], d[3]);
            if (ti != tj) {
                Cb[(size_t)gc * CDIM + gr]           = d[0];
                Cb[(size_t)(gc + 1) * CDIM + gr]     = d[1];
                Cb[(size_t)gc * CDIM + gr + 8]       = d[2];
                Cb[(size_t)(gc + 1) * CDIM + gr + 8] = d[3];
            }
        }
}

// ===========================================================================
// Stage 2: softmin rows of S -> bf16 hi/lo weights.
// ===========================================================================
__global__ void softmin_kernel() {
    const int b = blockIdx.y, r = blockIdx.x;
    const float* row = g_scores + ((size_t)b * CDIM + r) * CDIM;
    const int t = threadIdx.x;
    const int warp = t >> 5, lane = t & 31;

    float4 v = ((const float4*)row)[t];
    float mn = fminf(fminf(v.x, v.y), fminf(v.z, v.w));
#pragma unroll
    for (int o = 16; o > 0; o >>= 1)
        mn = fminf(mn, __shfl_xor_sync(0xffffffffu, mn, o));

    __shared__ float rmin[4], rsum[4];
    if (lane == 0) rmin[warp] = mn;
    __syncthreads();
    mn = fminf(fminf(rmin[0], rmin[1]), fminf(rmin[2], rmin[3]));

    float4 e;
    e.x = __expf(mn - v.x); e.y = __expf(mn - v.y);
    e.z = __expf(mn - v.z); e.w = __expf(mn - v.w);
    float s = e.x + e.y + e.z + e.w;
#pragma unroll
    for (int o = 16; o > 0; o >>= 1)
        s += __shfl_xor_sync(0xffffffffu, s, o);
    if (lane == 0) rsum[warp] = s;
    __syncthreads();
    s = rsum[0] + rsum[1] + rsum[2] + rsum[3];

    const float inv = __frcp_rn(s);
    unsigned short h[4], l[4];
    bsplit(e.x * inv, h[0], l[0]); bsplit(e.y * inv, h[1], l[1]);
    bsplit(e.z * inv, h[2], l[2]); bsplit(e.w * inv, h[3], l[3]);
    uint2 ph, pl;
    ph.x = h[0] | ((uint32_t)h[1] << 16); ph.y = h[2] | ((uint32_t)h[3] << 16);
    pl.x = l[0] | ((uint32_t)l[1] << 16); pl.y = l[2] | ((uint32_t)l[3] << 16);
    const size_t off = ((size_t)b * CDIM + r) * CDIM + t * 4;
    *(uint2*)(g_wh + off) = ph;
    *(uint2*)(g_wl + off) = pl;
}

// ===========================================================================
// Stage 3: out = beta * (W @ feat) + x.  128x256 CTA tile, BK=16, 2-stage.
// 8 warps (2M x 4N), warp tile 64x64. 96 MMAs per chunk per warp.
// A = W [c][d] hi/lo, B = feat^T [n][c] hi/lo.  NC = 512/16 = 32.
// ===========================================================================
__global__ __launch_bounds__(256)
void av_mma(const float* __restrict__ x, const float* __restrict__ beta,
            float* __restrict__ out) {
    __shared__ unsigned short SA[2][2][TSZ];     // 16 KB  (Ah, Al)
    __shared__ unsigned short SB[2][2][BTSZ];    // 32 KB  (Bh, Bl)

    const int b = blockIdx.z, nblk = blockIdx.x, mblk = blockIdx.y;
    const int t = threadIdx.x, lane = t & 31, wid = t >> 5;

    const unsigned short* Wsrc[2] = {
        g_wh + (size_t)(b * CDIM + mblk * 128) * CDIM,
        g_wl + (size_t)(b * CDIM + mblk * 128) * CDIM };
    const unsigned short* Fsrc[2] = {
        g_th + (size_t)(b * NDIM + nblk * 256) * CDIM,
        g_tl + (size_t)(b * NDIM + nblk * 256) * CDIM };

    // copy map
    const int crow = t >> 1, ckh = t & 1;             // A: rows 0..127
    const size_t goffA = (size_t)crow * CDIM + ckh * 8;
    const uint32_t soffA = tswz(crow, ckh);
    const int rb0 = crow, rb1 = crow + 128;           // B: rows 0..255
    const size_t goffB0 = (size_t)rb0 * CDIM + ckh * 8;
    const size_t goffB1 = (size_t)rb1 * CDIM + ckh * 8;
    const uint32_t soffB0 = tswz(rb0, ckh);
    const uint32_t soffB1 = tswz(rb1, ckh);

    const int wm = (wid & 1) * 64, wn = (wid >> 1) * 64;
    const int a_r = wm + (lane & 15), a_kh = lane >> 4;
    const int b_r = wn + (lane & 7) + ((lane >> 4) << 3), b_kh = (lane >> 3) & 1;

    float acc[4][8][4];
#pragma unroll
    for (int i = 0; i < 4; i++)
#pragma unroll
        for (int j = 0; j < 8; j++)
#pragma unroll
            for (int k = 0; k < 4; k++) acc[i][j][k] = 0.f;

    // prologue: chunk 0 -> stage 0
#pragma unroll
    for (int tau = 0; tau < 2; tau++) {
        cpa(smem_u32(&SA[0][tau][0]) + soffA, Wsrc[tau] + goffA);
        cpa(smem_u32(&SB[0][tau][0]) + soffB0, Fsrc[tau] + goffB0);
        cpa(smem_u32(&SB[0][tau][0]) + soffB1, Fsrc[tau] + goffB1);
    }
    CPC();

    const int NC = CDIM / 16;                       // 32
    for (int c = 0; c < NC; c++) {
        CPW(0);
        __syncthreads();                             // chunk c visible; c-1 consumed
        if (c + 1 < NC) {
            const int nb = (c + 1) & 1;
            const size_t go = (size_t)(c + 1) * 16;
#pragma unroll
            for (int tau = 0; tau < 2; tau++) {
                cpa(smem_u32(&SA[nb][tau][0]) + soffA, Wsrc[tau] + goffA + go);
                cpa(smem_u32(&SB[nb][tau][0]) + soffB0, Fsrc[tau] + goffB0 + go);
                cpa(smem_u32(&SB[nb][tau][0]) + soffB1, Fsrc[tau] + goffB1 + go);
            }
            CPC();
        }

        const int cb = c & 1;
        const uint32_t bAh = smem_u32(&SA[cb][0][0]);
        const uint32_t bAl = smem_u32(&SA[cb][1][0]);
        const uint32_t bBh = smem_u32(&SB[cb][0][0]);
        const uint32_t bBl = smem_u32(&SB[cb][1][0]);

        uint32_t AhF[4][4], AlF[4][4], BhF[4][4], BlF[4][4];
#pragma unroll
        for (int mi = 0; mi < 4; mi++)
            ldsm4(AhF[mi], bAh + tswz(a_r + 16 * mi, a_kh));
#pragma unroll
        for (int nj = 0; nj < 4; nj++)
            ldsm4(BhF[nj], bBh + tswz(b_r + 16 * nj, b_kh));
        // term 1: Ah x Bh
#pragma unroll
        for (int mi = 0; mi < 4; mi++)
#pragma unroll
            for (int ni = 0; ni < 8; ni++)
                mma16816(acc[mi][ni], AhF[mi], &BhF[ni >> 1][(ni & 1) * 2]);
        // term 2: Ah x Bl
#pragma unroll
        for (int nj = 0; nj < 4; nj++)
            ldsm4(BlF[nj], bBl + tswz(b_r + 16 * nj, b_kh));
#pragma unroll
        for (int mi = 0; mi < 4; mi++)
#pragma unroll
            for (int ni = 0; ni < 8; ni++)
                mma16816(acc[mi][ni], AhF[mi], &BlF[ni >> 1][(ni & 1) * 2]);
        // term 3: Al x Bh
#pragma unroll
        for (int mi = 0; mi < 4; mi++)
            ldsm4(AlF[mi], bAl + tswz(a_r + 16 * mi, a_kh));
#pragma unroll
        for (int mi = 0; mi < 4; mi++)
#pragma unroll
            for (int ni = 0; ni < 8; ni++)
                mma16816(acc[mi][ni], AlF[mi], &BhF[ni >> 1][(ni & 1) * 2]);
    }

    const float beta0 = beta[0];
    const int r0 = mblk * 128 + wm + (lane >> 2);     // channel
    const int c0 = nblk * 256 + wn + 2 * (lane & 3);  // spatial
#pragma unroll
    for (int mi = 0; mi < 4; mi++)
#pragma unroll
        for (int ni = 0; ni < 8; ni++) {
            const float* d = acc[mi][ni];
            const int gr = r0 + 16 * mi, gc = c0 + 8 * ni;
            const size_t o0 = ((size_t)(b * CDIM + gr) * NDIM) + gc;
            const size_t o1 = ((size_t)(b * CDIM + gr + 8) * NDIM) + gc;
            float2 x0 = *(const float2*)(x + o0);
            float2 x1 = *(const float2*)(x + o1);
            *(float2*)(out + o0) = make_float2(fmaf(beta0, d[0], x0.x),
                                               fmaf(beta0, d[1], x0.y));
            *(float2*)(out + o1) = make_float2(fmaf(beta0, d[2], x1.x),
                                               fmaf(beta0, d[3], x1.y));
        }
}

// ===========================================================================
extern "C" void kernel_launch(void* const* d_in, const int* in_sizes, int n_in,
                              void* d_out, int out_size) {
    (void)n_in; (void)out_size;
    const float* x    = (const float*)d_in[0];
    const float* beta = (const float*)d_in[1];
    if (in_sizes[0] == 1) { const float* tmp = x; x = beta; beta = tmp; }
    float* out = (float*)d_out;

    prep_kernel<<<dim3(NDIM / 32, CDIM / 32, BDIM), 256>>>(x);
    gram_mma<<<dim3(10, BDIM), 256>>>();
    softmin_kernel<<<dim3(CDIM, BDIM), 128>>>();
    av_mma<<<dim3(NDIM / 256, CDIM / 128, BDIM), 256>>>(x, beta, out);
}

// round 12
// speedup vs baseline: 1.1677x; 1.1677x over previous
#include <cuda_runtime.h>
#include <cuda_bf16.h>
#include <cstdint>

// ===========================================================================
// ChannelAttentionModule (DANet), B=32, C=512, N=H*W=1024, fp32.
//   S = feat @ feat^T ; W = softmax(rowmax(S)-S) = exp(rowmin-S)/sum ;
//   out = beta * (W @ feat) + x
// R12: av reverted to R10 (128x128, 3-stage — best known). gram re-tiled to
// 128x64 (640 CTAs): fixes the 320-CTA/296-slot wave quantization that made
// gram cost ~2x its balanced time; 4-stage pipeline (12KB/chunk x 4 = 48KB).
// ===========================================================================

#define BDIM 32
#define CDIM 512
#define NDIM 1024
#define TSZ   2048                 // shorts per 128x16 tile
#define BTSZ2 1024                 // shorts per 64x16 tile

// ---------------- scratch (static device globals: allowed) ----------------
__device__ float          g_scores[(size_t)BDIM * CDIM * CDIM];
__device__ __align__(16) unsigned short g_h [(size_t)BDIM * CDIM * NDIM]; // x hi  [b][c][n]
__device__ __align__(16) unsigned short g_l [(size_t)BDIM * CDIM * NDIM]; // x lo
__device__ __align__(16) unsigned short g_th[(size_t)BDIM * NDIM * CDIM]; // x^T hi [b][n][c]
__device__ __align__(16) unsigned short g_tl[(size_t)BDIM * NDIM * CDIM]; // x^T lo
__device__ __align__(16) unsigned short g_wh[(size_t)BDIM * CDIM * CDIM]; // W hi  [b][c][d]
__device__ __align__(16) unsigned short g_wl[(size_t)BDIM * CDIM * CDIM]; // W lo

// ---------------- helpers ---------------------------------------------------
__device__ __forceinline__ uint32_t smem_u32(const void* p) {
    uint32_t a;
    asm("{ .reg .u64 t; cvta.to.shared.u64 t, %1; cvt.u32.u64 %0, t; }"
        : "=r"(a) : "l"(p));
    return a;
}
__device__ __forceinline__ void ldsm4(uint32_t r[4], uint32_t addr) {
    asm volatile("ldmatrix.sync.aligned.m8n8.x4.shared.b16 {%0,%1,%2,%3}, [%4];"
                 : "=r"(r[0]), "=r"(r[1]), "=r"(r[2]), "=r"(r[3]) : "r"(addr));
}
__device__ __forceinline__ void mma16816(float d[4], const uint32_t a[4],
                                         const uint32_t b[2]) {
    asm volatile(
        "mma.sync.aligned.m16n8k16.row.col.f32.bf16.bf16.f32 "
        "{%0,%1,%2,%3}, {%4,%5,%6,%7}, {%8,%9}, {%0,%1,%2,%3};"
        : "+f"(d[0]), "+f"(d[1]), "+f"(d[2]), "+f"(d[3])
        : "r"(a[0]), "r"(a[1]), "r"(a[2]), "r"(a[3]), "r"(b[0]), "r"(b[1]));
}
__device__ __forceinline__ void cpa(uint32_t s, const void* g) {
    asm volatile("cp.async.cg.shared.global [%0], [%1], 16;" :: "r"(s), "l"(g));
}
#define CPC()  asm volatile("cp.async.commit_group;" ::: "memory")
#define CPW(n) asm volatile("cp.async.wait_group %0;" :: "n"(n) : "memory")

// Tile-local byte offset for (row, k-half): row stride 32B, halves swap
// every 4 rows -> conflict-free cp.async stores and ldmatrix reads.
__device__ __forceinline__ uint32_t tswz(int row, int kh) {
    return (uint32_t)(row * 32 + ((kh ^ ((row >> 2) & 1)) << 4));
}

__device__ __forceinline__ void bsplit(float v, unsigned short& h, unsigned short& l) {
    __nv_bfloat16 hh = __float2bfloat16_rn(v);
    float r = v - __bfloat162float(hh);
    __nv_bfloat16 ll = __float2bfloat16_rn(r);
    h = *reinterpret_cast<unsigned short*>(&hh);
    l = *reinterpret_cast<unsigned short*>(&ll);
}

// ===========================================================================
// Fused 3-term 128x128 GEMM mainloop, 3-stage pipeline (av — R10 proven).
// ===========================================================================
template <int NC, int LD>
__device__ __forceinline__ void gemm3(
    const unsigned short* __restrict__ Ah, const unsigned short* __restrict__ Al,
    const unsigned short* __restrict__ Bh, const unsigned short* __restrict__ Bl,
    unsigned short (*S)[4][TSZ],            // [3][4][TSZ]
    float acc[4][4][4])
{
    const int t = threadIdx.x, lane = t & 31, wid = t >> 5;
    const int crow = t >> 1, ckh = t & 1;
    const size_t goff = (size_t)crow * LD + ckh * 8;
    const uint32_t soff = tswz(crow, ckh);

    const int wm = (wid & 1) * 64, wn = (wid >> 1) * 32;
    const int a_r = wm + (lane & 15), a_kh = lane >> 4;
    const int b_r = wn + (lane & 7) + ((lane >> 4) << 3), b_kh = (lane >> 3) & 1;

    const unsigned short* src[4] = { Ah, Al, Bh, Bl };

#pragma unroll
    for (int pc = 0; pc < 2; pc++) {
        if (pc < NC) {
#pragma unroll
            for (int tau = 0; tau < 4; tau++)
                cpa(smem_u32(&S[pc][tau][0]) + soff, src[tau] + goff + pc * 16);
            CPC();
        }
    }

    for (int c = 0; c < NC; c++) {
        if (c + 1 < NC) { CPW(1); } else { CPW(0); }
        __syncthreads();
        if (c + 2 < NC) {
            const int nb = (c + 2) % 3;
            const size_t go = goff + (size_t)(c + 2) * 16;
#pragma unroll
            for (int tau = 0; tau < 4; tau++)
                cpa(smem_u32(&S[nb][tau][0]) + soff, src[tau] + go);
            CPC();
        }

        const int cb = c % 3;
        const uint32_t bAh = smem_u32(&S[cb][0][0]);
        const uint32_t bAl = smem_u32(&S[cb][1][0]);
        const uint32_t bBh = smem_u32(&S[cb][2][0]);
        const uint32_t bBl = smem_u32(&S[cb][3][0]);

        uint32_t AhF[4][4], AlF[4][4], BhF[2][4], BlF[2][4];
#pragma unroll
        for (int mi = 0; mi < 4; mi++)
            ldsm4(AhF[mi], bAh + tswz(a_r + 16 * mi, a_kh));
#pragma unroll
        for (int nj = 0; nj < 2; nj++)
            ldsm4(BhF[nj], bBh + tswz(b_r + 16 * nj, b_kh));
#pragma unroll
        for (int mi = 0; mi < 4; mi++)
#pragma unroll
            for (int ni = 0; ni < 4; ni++)
                mma16816(acc[mi][ni], AhF[mi], &BhF[ni >> 1][(ni & 1) * 2]);
#pragma unroll
        for (int nj = 0; nj < 2; nj++)
            ldsm4(BlF[nj], bBl + tswz(b_r + 16 * nj, b_kh));
#pragma unroll
        for (int mi = 0; mi < 4; mi++)
#pragma unroll
            for (int ni = 0; ni < 4; ni++)
                mma16816(acc[mi][ni], AhF[mi], &BlF[ni >> 1][(ni & 1) * 2]);
#pragma unroll
        for (int mi = 0; mi < 4; mi++)
            ldsm4(AlF[mi], bAl + tswz(a_r + 16 * mi, a_kh));
#pragma unroll
        for (int mi = 0; mi < 4; mi++)
#pragma unroll
            for (int ni = 0; ni < 4; ni++)
                mma16816(acc[mi][ni], AlF[mi], &BhF[ni >> 1][(ni & 1) * 2]);
    }
}

// ===========================================================================
// Stage 0: split + transpose:  x -> g_h/g_l ([c][n])  and  g_th/g_tl ([n][c])
// ===========================================================================
__global__ void prep_kernel(const float* __restrict__ x) {
    const int b = blockIdx.z, c0 = blockIdx.y * 32, n0 = blockIdx.x * 32;
    __shared__ float tile[32][33];
    const int t = threadIdx.x;
    const int i = t >> 3, j0 = (t & 7) * 4;

    const size_t src = ((size_t)(b * CDIM + c0 + i) * NDIM) + n0 + j0;
    float4 v = *(const float4*)(x + src);
    tile[i][j0 + 0] = v.x; tile[i][j0 + 1] = v.y;
    tile[i][j0 + 2] = v.z; tile[i][j0 + 3] = v.w;

    unsigned short h[4], l[4];
    bsplit(v.x, h[0], l[0]); bsplit(v.y, h[1], l[1]);
    bsplit(v.z, h[2], l[2]); bsplit(v.w, h[3], l[3]);
    uint2 ph, pl;
    ph.x = h[0] | ((uint32_t)h[1] << 16); ph.y = h[2] | ((uint32_t)h[3] << 16);
    pl.x = l[0] | ((uint32_t)l[1] << 16); pl.y = l[2] | ((uint32_t)l[3] << 16);
    *(uint2*)(g_h + src) = ph;
    *(uint2*)(g_l + src) = pl;

    __syncthreads();

    float f0 = tile[j0 + 0][i], f1 = tile[j0 + 1][i];
    float f2 = tile[j0 + 2][i], f3 = tile[j0 + 3][i];
    bsplit(f0, h[0], l[0]); bsplit(f1, h[1], l[1]);
    bsplit(f2, h[2], l[2]); bsplit(f3, h[3], l[3]);
    ph.x = h[0] | ((uint32_t)h[1] << 16); ph.y = h[2] | ((uint32_t)h[3] << 16);
    pl.x = l[0] | ((uint32_t)l[1] << 16); pl.y = l[2] | ((uint32_t)l[3] << 16);
    const size_t dst = ((size_t)(b * NDIM + n0 + i) * CDIM) + c0 + j0;
    *(uint2*)(g_th + dst) = ph;
    *(uint2*)(g_tl + dst) = pl;
}

// ===========================================================================
// Stage 1: Gram S = F F^T.  128(M) x 64(N) tiles, 20 upper-tri pairs/batch
// (tjn*64 >= ti*128), mirrored on write. 4-stage pipeline, NC = 64 chunks.
// 8 warps as 4M x 2N, warp tile 32x32. Per chunk: 8 ldsm, 24 MMAs.
// ===========================================================================
__global__ __launch_bounds__(256, 2)
void gram_mma() {
    __shared__ unsigned short SA[4][2][TSZ];     // 32 KB (Ah, Al)
    __shared__ unsigned short SB[4][2][BTSZ2];   // 16 KB (Bh, Bl)

    const int b = blockIdx.y;
    int p = blockIdx.x;                          // 0..19
    int ti = 0;
    while (p >= 8 - 2 * ti) { p -= 8 - 2 * ti; ti++; }
    const int tjn = 2 * ti + p;                  // 64-col block, tjn*64 >= ti*128

    const int t = threadIdx.x, lane = t & 31, wid = t >> 5;

    const unsigned short* srcA[2] = {
        g_h + (size_t)(b * CDIM + ti * 128) * NDIM,
        g_l + (size_t)(b * CDIM + ti * 128) * NDIM };
    const unsigned short* srcB[2] = {
        g_h + (size_t)(b * CDIM + tjn * 64) * NDIM,
        g_l + (size_t)(b * CDIM + tjn * 64) * NDIM };

    // copy map: A -> one 16B unit per (hi,lo); B -> one unit (half threads each)
    const int crow = t >> 1, ckh = t & 1;                 // A rows 0..127
    const size_t gA = (size_t)crow * NDIM + ckh * 8;
    const uint32_t sA = tswz(crow, ckh);
    const int bsel = t >> 7;                              // 0: Bh, 1: Bl
    const int bt = t & 127;
    const int brow = bt >> 1, bkh = bt & 1;               // B rows 0..63
    const size_t gB = (size_t)brow * NDIM + bkh * 8;
    const uint32_t sB = tswz(brow, bkh);

    const int wm = (wid & 3) * 32, wn = (wid >> 2) * 32;
    const int a_r = wm + (lane & 15), a_kh = lane >> 4;
    const int b_r = wn + (lane & 7) + ((lane >> 4) << 3), b_kh = (lane >> 3) & 1;

    float acc[2][4][4];
#pragma unroll
    for (int i = 0; i < 2; i++)
#pragma unroll
        for (int j = 0; j < 4; j++)
#pragma unroll
            for (int k = 0; k < 4; k++) acc[i][j][k] = 0.f;

    const int NC = NDIM / 16;                    // 64
    // prologue: chunks 0..2
#pragma unroll
    for (int pc = 0; pc < 3; pc++) {
        cpa(smem_u32(&SA[pc][0][0]) + sA, srcA[0] + gA + pc * 16);
        cpa(smem_u32(&SA[pc][1][0]) + sA, srcA[1] + gA + pc * 16);
        cpa(smem_u32(&SB[pc][bsel][0]) + sB, srcB[bsel] + gB + pc * 16);
        CPC();
    }

    for (int c = 0; c < NC; c++) {
        CPW(2);                                  // oldest (chunk c) complete
        __syncthreads();
        if (c + 3 < NC) {
            const int nb = (c + 3) & 3;
            const size_t go = (size_t)(c + 3) * 16;
            cpa(smem_u32(&SA[nb][0][0]) + sA, srcA[0] + gA + go);
            cpa(smem_u32(&SA[nb][1][0]) + sA, srcA[1] + gA + go);
            cpa(smem_u32(&SB[nb][bsel][0]) + sB, srcB[bsel] + gB + go);
        }
        CPC();                                   // may be empty: keeps group count

        const int cb = c & 3;
        const uint32_t bAh = smem_u32(&SA[cb][0][0]);
        const uint32_t bAl = smem_u32(&SA[cb][1][0]);
        const uint32_t bBh = smem_u32(&SB[cb][0][0]);
        const uint32_t bBl = smem_u32(&SB[cb][1][0]);

        uint32_t AhF[2][4], AlF[2][4], BhF[2][4], BlF[2][4];
#pragma unroll
        for (int mi = 0; mi < 2; mi++)
            ldsm4(AhF[mi], bAh + tswz(a_r + 16 * mi, a_kh));
#pragma unroll
        for (int nj = 0; nj < 2; nj++)
            ldsm4(BhF[nj], bBh + tswz(b_r + 16 * nj, b_kh));
#pragma unroll
        for (int mi = 0; mi < 2; mi++)
#pragma unroll
            for (int ni = 0; ni < 4; ni++)
                mma16816(acc[mi][ni], AhF[mi], &BhF[ni >> 1][(ni & 1) * 2]);
#pragma unroll
        for (int nj = 0; nj < 2; nj++)
            ldsm4(BlF[nj], bBl + tswz(b_r + 16 * nj, b_kh));
#pragma unroll
        for (int mi = 0; mi < 2; mi++)
#pragma unroll
            for (int ni = 0; ni < 4; ni++)
                mma16816(acc[mi][ni], AhF[mi], &BlF[ni >> 1][(ni & 1) * 2]);
#pragma unroll
        for (int mi = 0; mi < 2; mi++)
            ldsm4(AlF[mi], bAl + tswz(a_r + 16 * mi, a_kh));
#pragma unroll
        for (int mi = 0; mi < 2; mi++)
#pragma unroll
            for (int ni = 0; ni < 4; ni++)
                mma16816(acc[mi][ni], AlF[mi], &BhF[ni >> 1][(ni & 1) * 2]);
    }

    float* Cb = g_scores + (size_t)b * CDIM * CDIM;
    const int r0 = ti * 128 + wm + (lane >> 2);
    const int c0 = tjn * 64 + wn + 2 * (lane & 3);
#pragma unroll
    for (int mi = 0; mi < 2; mi++)
#pragma unroll
        for (int ni = 0; ni < 4; ni++) {
            const float* d = acc[mi][ni];
            const int gr = r0 + 16 * mi, gc = c0 + 8 * ni;
            *(float2*)&Cb[(size_t)gr * CDIM + gc]       = make_float2(d[0], d[1]);
            *(float2*)&Cb[(size_t)(gr + 8) * CDIM + gc] = make_float2(d[2], d[3]);
            // mirror (diagonal-band double/racing writes carry equal values)
            Cb[(size_t)gc * CDIM + gr]           = d[0];
            Cb[(size_t)(gc + 1) * CDIM + gr]     = d[1];
            Cb[(size_t)gc * CDIM + gr + 8]       = d[2];
            Cb[(size_t)(gc + 1) * CDIM + gr + 8] = d[3];
        }
}

// ===========================================================================
// Stage 2: softmin rows of S -> bf16 hi/lo weights.
// ===========================================================================
__global__ void softmin_kernel() {
    const int b = blockIdx.y, r = blockIdx.x;
    const float* row = g_scores + ((size_t)b * CDIM + r) * CDIM;
    const int t = threadIdx.x;
    const int warp = t >> 5, lane = t & 31;

    float4 v = ((const float4*)row)[t];
    float mn = fminf(fminf(v.x, v.y), fminf(v.z, v.w));
#pragma unroll
    for (int o = 16; o > 0; o >>= 1)
        mn = fminf(mn, __shfl_xor_sync(0xffffffffu, mn, o));

    __shared__ float rmin[4], rsum[4];
    if (lane == 0) rmin[warp] = mn;
    __syncthreads();
    mn = fminf(fminf(rmin[0], rmin[1]), fminf(rmin[2], rmin[3]));

    float4 e;
    e.x = __expf(mn - v.x); e.y = __expf(mn - v.y);
    e.z = __expf(mn - v.z); e.w = __expf(mn - v.w);
    float s = e.x + e.y + e.z + e.w;
#pragma unroll
    for (int o = 16; o > 0; o >>= 1)
        s += __shfl_xor_sync(0xffffffffu, s, o);
    if (lane == 0) rsum[warp] = s;
    __syncthreads();
    s = rsum[0] + rsum[1] + rsum[2] + rsum[3];

    const float inv = __frcp_rn(s);
    unsigned short h[4], l[4];
    bsplit(e.x * inv, h[0], l[0]); bsplit(e.y * inv, h[1], l[1]);
    bsplit(e.z * inv, h[2], l[2]); bsplit(e.w * inv, h[3], l[3]);
    uint2 ph, pl;
    ph.x = h[0] | ((uint32_t)h[1] << 16); ph.y = h[2] | ((uint32_t)h[3] << 16);
    pl.x = l[0] | ((uint32_t)l[1] << 16); pl.y = l[2] | ((uint32_t)l[3] << 16);
    const size_t off = ((size_t)b * CDIM + r) * CDIM + t * 4;
    *(uint2*)(g_wh + off) = ph;
    *(uint2*)(g_wl + off) = pl;
}

// ===========================================================================
// Stage 3: out = beta * (W @ feat) + x.  R10 config: 128x128, 3-stage.
// ===========================================================================
__global__ __launch_bounds__(256, 2)
void av_mma(const float* __restrict__ x, const float* __restrict__ beta,
            float* __restrict__ out) {
    __shared__ unsigned short S[3][4][TSZ];      // exactly 48 KB

    const int b = blockIdx.z, nblk = blockIdx.x, mblk = blockIdx.y;

    const unsigned short* Wh = g_wh + (size_t)(b * CDIM + mblk * 128) * CDIM;
    const unsigned short* Wl = g_wl + (size_t)(b * CDIM + mblk * 128) * CDIM;
    const unsigned short* Fh = g_th + (size_t)(b * NDIM + nblk * 128) * CDIM;
    const unsigned short* Fl = g_tl + (size_t)(b * NDIM + nblk * 128) * CDIM;

    float acc[4][4][4];
#pragma unroll
    for (int i = 0; i < 4; i++)
#pragma unroll
        for (int j = 0; j < 4; j++)
#pragma unroll
            for (int k = 0; k < 4; k++) acc[i][j][k] = 0.f;

    gemm3<32, CDIM>(Wh, Wl, Fh, Fl, S, acc);

    const int lane = threadIdx.x & 31, wid = threadIdx.x >> 5;
    const int wm = (wid & 1) * 64, wn = (wid >> 1) * 32;
    const float beta0 = beta[0];
    const int r0 = mblk * 128 + wm + (lane >> 2);     // channel
    const int c0 = nblk * 128 + wn + 2 * (lane & 3);  // spatial
#pragma unroll
    for (int mi = 0; mi < 4; mi++)
#pragma unroll
        for (int ni = 0; ni < 4; ni++) {
            const float* d = acc[mi][ni];
            const int gr = r0 + 16 * mi, gc = c0 + 8 * ni;
            const size_t o0 = ((size_t)(b * CDIM + gr) * NDIM) + gc;
            const size_t o1 = ((size_t)(b * CDIM + gr + 8) * NDIM) + gc;
            float2 x0 = *(const float2*)(x + o0);
            float2 x1 = *(const float2*)(x + o1);
            *(float2*)(out + o0) = make_float2(fmaf(beta0, d[0], x0.x),
                                               fmaf(beta0, d[1], x0.y));
            *(float2*)(out + o1) = make_float2(fmaf(beta0, d[2], x1.x),
                                               fmaf(beta0, d[3], x1.y));
        }
}

// ===========================================================================
extern "C" void kernel_launch(void* const* d_in, const int* in_sizes, int n_in,
                              void* d_out, int out_size) {
    (void)n_in; (void)out_size;
    const float* x    = (const float*)d_in[0];
    const float* beta = (const float*)d_in[1];
    if (in_sizes[0] == 1) { const float* tmp = x; x = beta; beta = tmp; }
    float* out = (float*)d_out;

    prep_kernel<<<dim3(NDIM / 32, CDIM / 32, BDIM), 256>>>(x);
    gram_mma<<<dim3(20, BDIM), 256>>>();
    softmin_kernel<<<dim3(CDIM, BDIM), 128>>>();
    av_mma<<<dim3(NDIM / 128, CDIM / 128, BDIM), 256>>>(x, beta, out);
}

// round 13
// speedup vs baseline: 1.1885x; 1.0178x over previous
#include <cuda_runtime.h>
#include <cuda_bf16.h>
#include <cstdint>

// ===========================================================================
// ChannelAttentionModule (DANet), B=32, C=512, N=H*W=1024, fp32.
//   S = feat @ feat^T ; W = softmax(rowmax(S)-S) = exp(rowmin-S)/sum ;
//   out = beta * (W @ feat) + x
// R13: av re-tiled to the PROVEN gram config (128x64 tiles, 4-stage
// pipeline): 2048 CTAs -> 6.9 waves (was 3.46) kills the ~16% wave-
// quantization tail. Shared templated mainloop for gram + av.
// ===========================================================================

#define BDIM 32
#define CDIM 512
#define NDIM 1024
#define TSZ   2048                 // shorts per 128x16 tile
#define BTSZ2 1024                 // shorts per 64x16 tile

// ---------------- scratch (static device globals: allowed) ----------------
__device__ float          g_scores[(size_t)BDIM * CDIM * CDIM];
__device__ __align__(16) unsigned short g_h [(size_t)BDIM * CDIM * NDIM]; // x hi  [b][c][n]
__device__ __align__(16) unsigned short g_l [(size_t)BDIM * CDIM * NDIM]; // x lo
__device__ __align__(16) unsigned short g_th[(size_t)BDIM * NDIM * CDIM]; // x^T hi [b][n][c]
__device__ __align__(16) unsigned short g_tl[(size_t)BDIM * NDIM * CDIM]; // x^T lo
__device__ __align__(16) unsigned short g_wh[(size_t)BDIM * CDIM * CDIM]; // W hi  [b][c][d]
__device__ __align__(16) unsigned short g_wl[(size_t)BDIM * CDIM * CDIM]; // W lo

// ---------------- helpers ---------------------------------------------------
__device__ __forceinline__ uint32_t smem_u32(const void* p) {
    uint32_t a;
    asm("{ .reg .u64 t; cvta.to.shared.u64 t, %1; cvt.u32.u64 %0, t; }"
        : "=r"(a) : "l"(p));
    return a;
}
__device__ __forceinline__ void ldsm4(uint32_t r[4], uint32_t addr) {
    asm volatile("ldmatrix.sync.aligned.m8n8.x4.shared.b16 {%0,%1,%2,%3}, [%4];"
                 : "=r"(r[0]), "=r"(r[1]), "=r"(r[2]), "=r"(r[3]) : "r"(addr));
}
__device__ __forceinline__ void mma16816(float d[4], const uint32_t a[4],
                                         const uint32_t b[2]) {
    asm volatile(
        "mma.sync.aligned.m16n8k16.row.col.f32.bf16.bf16.f32 "
        "{%0,%1,%2,%3}, {%4,%5,%6,%7}, {%8,%9}, {%0,%1,%2,%3};"
        : "+f"(d[0]), "+f"(d[1]), "+f"(d[2]), "+f"(d[3])
        : "r"(a[0]), "r"(a[1]), "r"(a[2]), "r"(a[3]), "r"(b[0]), "r"(b[1]));
}
__device__ __forceinline__ void cpa(uint32_t s, const void* g) {
    asm volatile("cp.async.cg.shared.global [%0], [%1], 16;" :: "r"(s), "l"(g));
}
#define CPC()  asm volatile("cp.async.commit_group;" ::: "memory")
#define CPW(n) asm volatile("cp.async.wait_group %0;" :: "n"(n) : "memory")

// Tile-local byte offset for (row, k-half): row stride 32B, halves swap
// every 4 rows -> conflict-free cp.async stores and ldmatrix reads.
__device__ __forceinline__ uint32_t tswz(int row, int kh) {
    return (uint32_t)(row * 32 + ((kh ^ ((row >> 2) & 1)) << 4));
}

__device__ __forceinline__ void bsplit(float v, unsigned short& h, unsigned short& l) {
    __nv_bfloat16 hh = __float2bfloat16_rn(v);
    float r = v - __bfloat162float(hh);
    __nv_bfloat16 ll = __float2bfloat16_rn(r);
    h = *reinterpret_cast<unsigned short*>(&hh);
    l = *reinterpret_cast<unsigned short*>(&ll);
}

// ===========================================================================
// Shared fused 3-term 128(M) x 64(N) GEMM mainloop, 4-stage pipeline.
// 8 warps as 4M x 2N, warp tile 32x32. Per chunk: 8 ldsm, 24 MMAs.
// A rows: 128 (stride LD), B rows: 64 (stride LD). acc[2][4][4].
// ===========================================================================
template <int LD, int NC>
__device__ __forceinline__ void gemm64(
    const unsigned short* __restrict__ Ah, const unsigned short* __restrict__ Al,
    const unsigned short* __restrict__ Bh, const unsigned short* __restrict__ Bl,
    unsigned short (*SA)[2][TSZ],           // [4][2][TSZ]
    unsigned short (*SB)[2][BTSZ2],         // [4][2][BTSZ2]
    float acc[2][4][4])
{
    const int t = threadIdx.x, lane = t & 31, wid = t >> 5;

    const unsigned short* srcA[2] = { Ah, Al };
    const unsigned short* srcB[2] = { Bh, Bl };

    // copy map: A -> one 16B unit per (hi,lo); B -> one unit (half threads each)
    const int crow = t >> 1, ckh = t & 1;                 // A rows 0..127
    const size_t gA = (size_t)crow * LD + ckh * 8;
    const uint32_t sA = tswz(crow, ckh);
    const int bsel = t >> 7;                              // 0: Bh, 1: Bl
    const int bt = t & 127;
    const int brow = bt >> 1, bkh = bt & 1;               // B rows 0..63
    const size_t gB = (size_t)brow * LD + bkh * 8;
    const uint32_t sB = tswz(brow, bkh);

    const int wm = (wid & 3) * 32, wn = (wid >> 2) * 32;
    const int a_r = wm + (lane & 15), a_kh = lane >> 4;
    const int b_r = wn + (lane & 7) + ((lane >> 4) << 3), b_kh = (lane >> 3) & 1;

    // prologue: chunks 0..2
#pragma unroll
    for (int pc = 0; pc < 3; pc++) {
        cpa(smem_u32(&SA[pc][0][0]) + sA, srcA[0] + gA + pc * 16);
        cpa(smem_u32(&SA[pc][1][0]) + sA, srcA[1] + gA + pc * 16);
        cpa(smem_u32(&SB[pc][bsel][0]) + sB, srcB[bsel] + gB + pc * 16);
        CPC();
    }

    for (int c = 0; c < NC; c++) {
        CPW(2);                                  // oldest (chunk c) complete
        __syncthreads();
        if (c + 3 < NC) {
            const int nb = (c + 3) & 3;
            const size_t go = (size_t)(c + 3) * 16;
            cpa(smem_u32(&SA[nb][0][0]) + sA, srcA[0] + gA + go);
            cpa(smem_u32(&SA[nb][1][0]) + sA, srcA[1] + gA + go);
            cpa(smem_u32(&SB[nb][bsel][0]) + sB, srcB[bsel] + gB + go);
        }
        CPC();                                   // may be empty: keeps group count

        const int cb = c & 3;
        const uint32_t bAh = smem_u32(&SA[cb][0][0]);
        const uint32_t bAl = smem_u32(&SA[cb][1][0]);
        const uint32_t bBh = smem_u32(&SB[cb][0][0]);
        const uint32_t bBl = smem_u32(&SB[cb][1][0]);

        uint32_t AhF[2][4], AlF[2][4], BhF[2][4], BlF[2][4];
#pragma unroll
        for (int mi = 0; mi < 2; mi++)
            ldsm4(AhF[mi], bAh + tswz(a_r + 16 * mi, a_kh));
#pragma unroll
        for (int nj = 0; nj < 2; nj++)
            ldsm4(BhF[nj], bBh + tswz(b_r + 16 * nj, b_kh));
#pragma unroll
        for (int mi = 0; mi < 2; mi++)
#pragma unroll
            for (int ni = 0; ni < 4; ni++)
                mma16816(acc[mi][ni], AhF[mi], &BhF[ni >> 1][(ni & 1) * 2]);
#pragma unroll
        for (int nj = 0; nj < 2; nj++)
            ldsm4(BlF[nj], bBl + tswz(b_r + 16 * nj, b_kh));
#pragma unroll
        for (int mi = 0; mi < 2; mi++)
#pragma unroll
            for (int ni = 0; ni < 4; ni++)
                mma16816(acc[mi][ni], AhF[mi], &BlF[ni >> 1][(ni & 1) * 2]);
#pragma unroll
        for (int mi = 0; mi < 2; mi++)
            ldsm4(AlF[mi], bAl + tswz(a_r + 16 * mi, a_kh));
#pragma unroll
        for (int mi = 0; mi < 2; mi++)
#pragma unroll
            for (int ni = 0; ni < 4; ni++)
                mma16816(acc[mi][ni], AlF[mi], &BhF[ni >> 1][(ni & 1) * 2]);
    }
}

// ===========================================================================
// Stage 0: split + transpose:  x -> g_h/g_l ([c][n])  and  g_th/g_tl ([n][c])
// ===========================================================================
__global__ void prep_kernel(const float* __restrict__ x) {
    const int b = blockIdx.z, c0 = blockIdx.y * 32, n0 = blockIdx.x * 32;
    __shared__ float tile[32][33];
    const int t = threadIdx.x;
    const int i = t >> 3, j0 = (t & 7) * 4;

    const size_t src = ((size_t)(b * CDIM + c0 + i) * NDIM) + n0 + j0;
    float4 v = *(const float4*)(x + src);
    tile[i][j0 + 0] = v.x; tile[i][j0 + 1] = v.y;
    tile[i][j0 + 2] = v.z; tile[i][j0 + 3] = v.w;

    unsigned short h[4], l[4];
    bsplit(v.x, h[0], l[0]); bsplit(v.y, h[1], l[1]);
    bsplit(v.z, h[2], l[2]); bsplit(v.w, h[3], l[3]);
    uint2 ph, pl;
    ph.x = h[0] | ((uint32_t)h[1] << 16); ph.y = h[2] | ((uint32_t)h[3] << 16);
    pl.x = l[0] | ((uint32_t)l[1] << 16); pl.y = l[2] | ((uint32_t)l[3] << 16);
    *(uint2*)(g_h + src) = ph;
    *(uint2*)(g_l + src) = pl;

    __syncthreads();

    float f0 = tile[j0 + 0][i], f1 = tile[j0 + 1][i];
    float f2 = tile[j0 + 2][i], f3 = tile[j0 + 3][i];
    bsplit(f0, h[0], l[0]); bsplit(f1, h[1], l[1]);
    bsplit(f2, h[2], l[2]); bsplit(f3, h[3], l[3]);
    ph.x = h[0] | ((uint32_t)h[1] << 16); ph.y = h[2] | ((uint32_t)h[3] << 16);
    pl.x = l[0] | ((uint32_t)l[1] << 16); pl.y = l[2] | ((uint32_t)l[3] << 16);
    const size_t dst = ((size_t)(b * NDIM + n0 + i) * CDIM) + c0 + j0;
    *(uint2*)(g_th + dst) = ph;
    *(uint2*)(g_tl + dst) = pl;
}

// ===========================================================================
// Stage 1: Gram S = F F^T.  128x64 tiles, 20 upper-tri pairs/batch, mirrored.
// ===========================================================================
__global__ __launch_bounds__(256, 2)
void gram_mma() {
    __shared__ unsigned short SA[4][2][TSZ];     // 32 KB (Ah, Al)
    __shared__ unsigned short SB[4][2][BTSZ2];   // 16 KB (Bh, Bl)

    const int b = blockIdx.y;
    int p = blockIdx.x;                          // 0..19
    int ti = 0;
    while (p >= 8 - 2 * ti) { p -= 8 - 2 * ti; ti++; }
    const int tjn = 2 * ti + p;                  // 64-col block, tjn*64 >= ti*128

    float acc[2][4][4];
#pragma unroll
    for (int i = 0; i < 2; i++)
#pragma unroll
        for (int j = 0; j < 4; j++)
#pragma unroll
            for (int k = 0; k < 4; k++) acc[i][j][k] = 0.f;

    gemm64<NDIM, NDIM / 16>(
        g_h + (size_t)(b * CDIM + ti * 128) * NDIM,
        g_l + (size_t)(b * CDIM + ti * 128) * NDIM,
        g_h + (size_t)(b * CDIM + tjn * 64) * NDIM,
        g_l + (size_t)(b * CDIM + tjn * 64) * NDIM,
        SA, SB, acc);

    const int lane = threadIdx.x & 31, wid = threadIdx.x >> 5;
    const int wm = (wid & 3) * 32, wn = (wid >> 2) * 32;
    float* Cb = g_scores + (size_t)b * CDIM * CDIM;
    const int r0 = ti * 128 + wm + (lane >> 2);
    const int c0 = tjn * 64 + wn + 2 * (lane & 3);
#pragma unroll
    for (int mi = 0; mi < 2; mi++)
#pragma unroll
        for (int ni = 0; ni < 4; ni++) {
            const float* d = acc[mi][ni];
            const int gr = r0 + 16 * mi, gc = c0 + 8 * ni;
            *(float2*)&Cb[(size_t)gr * CDIM + gc]       = make_float2(d[0], d[1]);
            *(float2*)&Cb[(size_t)(gr + 8) * CDIM + gc] = make_float2(d[2], d[3]);
            // mirror (diagonal-band double/racing writes carry equal values)
            Cb[(size_t)gc * CDIM + gr]           = d[0];
            Cb[(size_t)(gc + 1) * CDIM + gr]     = d[1];
            Cb[(size_t)gc * CDIM + gr + 8]       = d[2];
            Cb[(size_t)(gc + 1) * CDIM + gr + 8] = d[3];
        }
}

// ===========================================================================
// Stage 2: softmin rows of S -> bf16 hi/lo weights.
// ===========================================================================
__global__ void softmin_kernel() {
    const int b = blockIdx.y, r = blockIdx.x;
    const float* row = g_scores + ((size_t)b * CDIM + r) * CDIM;
    const int t = threadIdx.x;
    const int warp = t >> 5, lane = t & 31;

    float4 v = ((const float4*)row)[t];
    float mn = fminf(fminf(v.x, v.y), fminf(v.z, v.w));
#pragma unroll
    for (int o = 16; o > 0; o >>= 1)
        mn = fminf(mn, __shfl_xor_sync(0xffffffffu, mn, o));

    __shared__ float rmin[4], rsum[4];
    if (lane == 0) rmin[warp] = mn;
    __syncthreads();
    mn = fminf(fminf(rmin[0], rmin[1]), fminf(rmin[2], rmin[3]));

    float4 e;
    e.x = __expf(mn - v.x); e.y = __expf(mn - v.y);
    e.z = __expf(mn - v.z); e.w = __expf(mn - v.w);
    float s = e.x + e.y + e.z + e.w;
#pragma unroll
    for (int o = 16; o > 0; o >>= 1)
        s += __shfl_xor_sync(0xffffffffu, s, o);
    if (lane == 0) rsum[warp] = s;
    __syncthreads();
    s = rsum[0] + rsum[1] + rsum[2] + rsum[3];

    const float inv = __frcp_rn(s);
    unsigned short h[4], l[4];
    bsplit(e.x * inv, h[0], l[0]); bsplit(e.y * inv, h[1], l[1]);
    bsplit(e.z * inv, h[2], l[2]); bsplit(e.w * inv, h[3], l[3]);
    uint2 ph, pl;
    ph.x = h[0] | ((uint32_t)h[1] << 16); ph.y = h[2] | ((uint32_t)h[3] << 16);
    pl.x = l[0] | ((uint32_t)l[1] << 16); pl.y = l[2] | ((uint32_t)l[3] << 16);
    const size_t off = ((size_t)b * CDIM + r) * CDIM + t * 4;
    *(uint2*)(g_wh + off) = ph;
    *(uint2*)(g_wl + off) = pl;
}

// ===========================================================================
// Stage 3: out = beta * (W @ feat) + x.  128x64 tiles, 4-stage, 2048 CTAs.
// A = W [c][d] hi/lo (LD=CDIM), B = feat^T [n][c] hi/lo (LD=CDIM), NC=32.
// ===========================================================================
__global__ __launch_bounds__(256, 2)
void av_mma(const float* __restrict__ x, const float* __restrict__ beta,
            float* __restrict__ out) {
    __shared__ unsigned short SA[4][2][TSZ];     // 32 KB (Wh, Wl)
    __shared__ unsigned short SB[4][2][BTSZ2];   // 16 KB (Fh, Fl)

    const int b = blockIdx.z, nblk = blockIdx.x, mblk = blockIdx.y;

    float acc[2][4][4];
#pragma unroll
    for (int i = 0; i < 2; i++)
#pragma unroll
        for (int j = 0; j < 4; j++)
#pragma unroll
            for (int k = 0; k < 4; k++) acc[i][j][k] = 0.f;

    gemm64<CDIM, CDIM / 16>(
        g_wh + (size_t)(b * CDIM + mblk * 128) * CDIM,
        g_wl + (size_t)(b * CDIM + mblk * 128) * CDIM,
        g_th + (size_t)(b * NDIM + nblk * 64) * CDIM,
        g_tl + (size_t)(b * NDIM + nblk * 64) * CDIM,
        SA, SB, acc);

    const int lane = threadIdx.x & 31, wid = threadIdx.x >> 5;
    const int wm = (wid & 3) * 32, wn = (wid >> 2) * 32;
    const float beta0 = beta[0];
    const int r0 = mblk * 128 + wm + (lane >> 2);     // channel
    const int c0 = nblk * 64 + wn + 2 * (lane & 3);   // spatial
#pragma unroll
    for (int mi = 0; mi < 2; mi++)
#pragma unroll
        for (int ni = 0; ni < 4; ni++) {
            const float* d = acc[mi][ni];
            const int gr = r0 + 16 * mi, gc = c0 + 8 * ni;
            const size_t o0 = ((size_t)(b * CDIM + gr) * NDIM) + gc;
            const size_t o1 = ((size_t)(b * CDIM + gr + 8) * NDIM) + gc;
            float2 x0 = *(const float2*)(x + o0);
            float2 x1 = *(const float2*)(x + o1);
            *(float2*)(out + o0) = make_float2(fmaf(beta0, d[0], x0.x),
                                               fmaf(beta0, d[1], x0.y));
            *(float2*)(out + o1) = make_float2(fmaf(beta0, d[2], x1.x),
                                               fmaf(beta0, d[3], x1.y));
        }
}

// ===========================================================================
extern "C" void kernel_launch(void* const* d_in, const int* in_sizes, int n_in,
                              void* d_out, int out_size) {
    (void)n_in; (void)out_size;
    const float* x    = (const float*)d_in[0];
    const float* beta = (const float*)d_in[1];
    if (in_sizes[0] == 1) { const float* tmp = x; x = beta; beta = tmp; }
    float* out = (float*)d_out;

    prep_kernel<<<dim3(NDIM / 32, CDIM / 32, BDIM), 256>>>(x);
    gram_mma<<<dim3(20, BDIM), 256>>>();
    softmin_kernel<<<dim3(CDIM, BDIM), 128>>>();
    av_mma<<<dim3(NDIM / 64, CDIM / 128, BDIM), 256>>>(x, beta, out);
}